// round 1
// baseline (speedup 1.0000x reference)
#include <cuda_runtime.h>
#include <math.h>
#include <stddef.h>

// Problem constants
#define BATCH 16
#define DIM   512
#define HW    1024      // 32x32
#define NPIX  1024      // GEMM N per batch
#define DWC   992       // sum of DIMS = 32+64+128+256+512

// -------- scratch (device globals; no allocations allowed) --------
__device__ float g_ln  [(size_t)BATCH*DIM *HW];   // LN1 out
__device__ float g_fused[(size_t)BATCH*1024*HW];  // pin out (2*DIM=1024 ch)
__device__ float g_dw  [(size_t)BATCH*DWC *HW];   // depthwise out (+bias)
__device__ float g_y0  [(size_t)BATCH* 32 *HW];
__device__ float g_y1  [(size_t)BATCH* 64 *HW];
__device__ float g_y2  [(size_t)BATCH*128 *HW];
__device__ float g_y3  [(size_t)BATCH*256 *HW];
__device__ float g_y4  [(size_t)BATCH*512 *HW];
__device__ float g_x1  [(size_t)BATCH*DIM *HW];   // x + g1*gnconv(x)
__device__ float g_ln2 [(size_t)BATCH*DIM *HW];   // LN2 out
__device__ float g_h   [(size_t)BATCH*2048*HW];   // fc1+gelu out

// ---------------- LayerNorm over channel dim (NCHW) ----------------
// grid: BATCH*32 blocks (each block: one batch, 32-pixel tile), block (32,8)
__global__ __launch_bounds__(256) void ln_kernel(
    const float* __restrict__ x, const float* __restrict__ w,
    const float* __restrict__ b, float* __restrict__ out)
{
    int bi  = blockIdx.x >> 5;          // batch
    int px0 = (blockIdx.x & 31) << 5;   // pixel tile start
    int tx = threadIdx.x;               // pixel within tile (0..31)
    int ty = threadIdx.y;               // channel phase (0..7)
    const float* xb = x + (size_t)bi*DIM*HW + px0 + tx;

    float s = 0.f, ss = 0.f;
    for (int c = ty; c < DIM; c += 8) {
        float v = xb[(size_t)c*HW];
        s += v; ss += v*v;
    }
    __shared__ float Ss[8][32], Sq[8][32];
    Ss[ty][tx] = s; Sq[ty][tx] = ss;
    __syncthreads();
    if (ty == 0) {
        float a = 0.f, q = 0.f;
        #pragma unroll
        for (int i = 0; i < 8; i++) { a += Ss[i][tx]; q += Sq[i][tx]; }
        float mean = a * (1.0f/DIM);
        float var  = q * (1.0f/DIM) - mean*mean;
        Ss[0][tx] = mean;
        Sq[0][tx] = rsqrtf(var + 1e-6f);
    }
    __syncthreads();
    float mean = Ss[0][tx], inv = Sq[0][tx];
    float* ob = out + (size_t)bi*DIM*HW + px0 + tx;
    for (int c = ty; c < DIM; c += 8) {
        float v = xb[(size_t)c*HW];
        ob[(size_t)c*HW] = w[c] * ((v - mean) * inv) + b[c];
    }
}

// -------- 7x7 depthwise conv (pad 3) on abc = fused[:, 32:1024] --------
// grid (DWC, BATCH), 256 threads; writes g_dw with bias added (SCALE=1.0)
__global__ __launch_bounds__(256) void dwconv_kernel(
    const float* __restrict__ fused, const float* __restrict__ w,
    const float* __restrict__ bias, float* __restrict__ out)
{
    int ch = blockIdx.x;
    int bi = blockIdx.y;
    const float* ip = fused + ((size_t)bi*1024 + 32 + ch) * HW;
    __shared__ float tile[38][38];
    __shared__ float kw[49];
    int tid = threadIdx.x;
    if (tid < 49) kw[tid] = w[(size_t)ch*49 + tid];
    for (int i = tid; i < 38*38; i += 256) {
        int r = i / 38 - 3, c = i % 38 - 3;
        tile[i/38][i%38] = (r >= 0 && r < 32 && c >= 0 && c < 32) ? ip[r*32 + c] : 0.f;
    }
    __syncthreads();
    float bv = bias[ch];
    float* op = out + ((size_t)bi*DWC + ch) * HW;
    for (int i = tid; i < 1024; i += 256) {
        int r = i >> 5, c = i & 31;
        float acc = bv;
        #pragma unroll
        for (int kr = 0; kr < 7; kr++)
            #pragma unroll
            for (int kc = 0; kc < 7; kc++)
                acc += tile[r+kr][c+kc] * kw[kr*7 + kc];
        op[i] = acc;   // SCALE == 1.0
    }
}

// -------- y0 = pwa * dw_list[0]  (first 32 channels of each) --------
__global__ __launch_bounds__(256) void gate0_kernel(
    const float* __restrict__ fused, const float* __restrict__ dw,
    float* __restrict__ y0)
{
    size_t i = (size_t)blockIdx.x * 256 + threadIdx.x;   // over BATCH*32*HW
    size_t bi = i / (32*HW);
    size_t r  = i % (32*HW);
    y0[i] = fused[bi*(size_t)1024*HW + r] * dw[bi*(size_t)DWC*HW + r];
}

// ---------------- Generic SGEMM: out[b] = W(MxK) @ X[b](KxN) + bias ----------------
// N fixed = 1024. grid (N/64, M/64, BATCH), 256 threads, 64x64x16 tiles, 4x4/thread.
// Epilogue: optional gate multiply (dw slice), gelu, residual (resid + gvec[m]*v).
__global__ __launch_bounds__(256) void gemm_kernel(
    const float* __restrict__ W, const float* __restrict__ X,
    const float* __restrict__ bias, float* __restrict__ out,
    int M, int K,
    const float* __restrict__ gate, int gate_chofs,
    const float* __restrict__ resid, const float* __restrict__ gvec,
    int do_gelu)
{
    const int N = NPIX;
    int bi = blockIdx.z;
    int m0 = blockIdx.y * 64, n0 = blockIdx.x * 64;
    const float* Xb = X + (size_t)bi * K * N;
    float* Ob = out + (size_t)bi * M * N;

    __shared__ float Ws[16][68];   // padded (16B-aligned rows, 2-way store conflict max)
    __shared__ float Xs[16][64];

    int tid = threadIdx.x;
    int ty = tid >> 4, tx = tid & 15;
    float acc[4][4] = {};

    for (int k0 = 0; k0 < K; k0 += 16) {
        #pragma unroll
        for (int i = 0; i < 4; i++) {
            int idx = tid + i*256;
            int m = idx >> 4, kk = idx & 15;
            Ws[kk][m] = W[(size_t)(m0 + m) * K + (k0 + kk)];
        }
        #pragma unroll
        for (int i = 0; i < 4; i++) {
            int idx = tid + i*256;
            int kk = idx >> 6, n = idx & 63;
            Xs[kk][n] = Xb[(size_t)(k0 + kk) * N + (n0 + n)];
        }
        __syncthreads();
        #pragma unroll
        for (int k = 0; k < 16; k++) {
            float4 av = *(const float4*)&Ws[k][ty*4];
            float4 bv = *(const float4*)&Xs[k][tx*4];
            float a[4] = {av.x, av.y, av.z, av.w};
            float bb[4] = {bv.x, bv.y, bv.z, bv.w};
            #pragma unroll
            for (int i = 0; i < 4; i++)
                #pragma unroll
                for (int j = 0; j < 4; j++)
                    acc[i][j] += a[i] * bb[j];
        }
        __syncthreads();
    }

    #pragma unroll
    for (int i = 0; i < 4; i++) {
        int m = m0 + ty*4 + i;
        float bval = bias[m];
        #pragma unroll
        for (int j = 0; j < 4; j++) {
            int n = n0 + tx*4 + j;
            float v = acc[i][j] + bval;
            if (gate)
                v *= gate[((size_t)bi*DWC + gate_chofs + m) * N + n];
            if (do_gelu)
                v = 0.5f * v * (1.0f + erff(v * 0.70710678118654752f));
            if (resid)
                v = resid[((size_t)bi*M + m) * N + n] + gvec[m] * v;
            Ob[(size_t)m * N + n] = v;
        }
    }
}

// ---------------- host launch ----------------
extern "C" void kernel_launch(void* const* d_in, const int* in_sizes, int n_in,
                              void* d_out, int out_size)
{
    (void)in_sizes; (void)n_in; (void)out_size;
    const float* x      = (const float*)d_in[0];
    const float* ln1_w  = (const float*)d_in[1];
    const float* ln1_b  = (const float*)d_in[2];
    const float* pin_w  = (const float*)d_in[3];
    const float* pin_b  = (const float*)d_in[4];
    const float* dw_w   = (const float*)d_in[5];
    const float* dw_b   = (const float*)d_in[6];
    const float* pw0_w  = (const float*)d_in[7];
    const float* pw0_b  = (const float*)d_in[8];
    const float* pw1_w  = (const float*)d_in[9];
    const float* pw1_b  = (const float*)d_in[10];
    const float* pw2_w  = (const float*)d_in[11];
    const float* pw2_b  = (const float*)d_in[12];
    const float* pw3_w  = (const float*)d_in[13];
    const float* pw3_b  = (const float*)d_in[14];
    const float* pout_w = (const float*)d_in[15];
    const float* pout_b = (const float*)d_in[16];
    const float* ln2_w  = (const float*)d_in[17];
    const float* ln2_b  = (const float*)d_in[18];
    const float* fc1_w  = (const float*)d_in[19];
    const float* fc1_b  = (const float*)d_in[20];
    const float* fc2_w  = (const float*)d_in[21];
    const float* fc2_b  = (const float*)d_in[22];
    const float* g1     = (const float*)d_in[23];
    const float* g2     = (const float*)d_in[24];
    float* out = (float*)d_out;

    float *p_ln, *p_fused, *p_dw, *p_y0, *p_y1, *p_y2, *p_y3, *p_y4, *p_x1, *p_ln2, *p_h;
    cudaGetSymbolAddress((void**)&p_ln,    g_ln);
    cudaGetSymbolAddress((void**)&p_fused, g_fused);
    cudaGetSymbolAddress((void**)&p_dw,    g_dw);
    cudaGetSymbolAddress((void**)&p_y0,    g_y0);
    cudaGetSymbolAddress((void**)&p_y1,    g_y1);
    cudaGetSymbolAddress((void**)&p_y2,    g_y2);
    cudaGetSymbolAddress((void**)&p_y3,    g_y3);
    cudaGetSymbolAddress((void**)&p_y4,    g_y4);
    cudaGetSymbolAddress((void**)&p_x1,    g_x1);
    cudaGetSymbolAddress((void**)&p_ln2,   g_ln2);
    cudaGetSymbolAddress((void**)&p_h,     g_h);

    dim3 lnBlock(32, 8);

    // 1) LN1
    ln_kernel<<<BATCH*32, lnBlock>>>(x, ln1_w, ln1_b, p_ln);
    // 2) pin: fused = pin_w(1024x512) @ ln1
    gemm_kernel<<<dim3(16,16,BATCH), 256>>>(pin_w, p_ln, pin_b, p_fused, 1024, 512,
                                            nullptr, 0, nullptr, nullptr, 0);
    // 3) depthwise 7x7 on abc (+bias)
    dwconv_kernel<<<dim3(DWC, BATCH), 256>>>(p_fused, dw_w, dw_b, p_dw);
    // 4) y0 = pwa * dw[0:32]
    gate0_kernel<<<(BATCH*32*HW)/256, 256>>>(p_fused, p_dw, p_y0);
    // 5..8) gating chain: y_{i+1} = (pw_i @ y_i + b) * dw slice
    gemm_kernel<<<dim3(16,1,BATCH), 256>>>(pw0_w, p_y0, pw0_b, p_y1,  64,  32,
                                           p_dw,  32, nullptr, nullptr, 0);
    gemm_kernel<<<dim3(16,2,BATCH), 256>>>(pw1_w, p_y1, pw1_b, p_y2, 128,  64,
                                           p_dw,  96, nullptr, nullptr, 0);
    gemm_kernel<<<dim3(16,4,BATCH), 256>>>(pw2_w, p_y2, pw2_b, p_y3, 256, 128,
                                           p_dw, 224, nullptr, nullptr, 0);
    gemm_kernel<<<dim3(16,8,BATCH), 256>>>(pw3_w, p_y3, pw3_b, p_y4, 512, 256,
                                           p_dw, 480, nullptr, nullptr, 0);
    // 9) pout + first residual: x1 = x + g1 * (pout_w @ y4 + pout_b)
    gemm_kernel<<<dim3(16,8,BATCH), 256>>>(pout_w, p_y4, pout_b, p_x1, 512, 512,
                                           nullptr, 0, x, g1, 0);
    // 10) LN2
    ln_kernel<<<BATCH*32, lnBlock>>>(p_x1, ln2_w, ln2_b, p_ln2);
    // 11) fc1 + exact GELU
    gemm_kernel<<<dim3(16,32,BATCH), 256>>>(fc1_w, p_ln2, fc1_b, p_h, 2048, 512,
                                            nullptr, 0, nullptr, nullptr, 1);
    // 12) fc2 + second residual -> out
    gemm_kernel<<<dim3(16,8,BATCH), 256>>>(fc2_w, p_h, fc2_b, out, 512, 2048,
                                           nullptr, 0, p_x1, g2, 0);
}

// round 2
// speedup vs baseline: 2.5462x; 2.5462x over previous
#include <cuda_runtime.h>
#include <cuda_bf16.h>
#include <math.h>
#include <stddef.h>
#include <stdint.h>

// Problem constants
#define BATCH 16
#define DIM   512
#define HW    1024      // 32x32
#define NPIX  1024      // GEMM N per batch
#define DWC   992       // sum of DIMS = 32+64+128+256+512

// -------- scratch (device globals; no allocations allowed) --------
__device__ float g_ln  [(size_t)BATCH*DIM *HW];   // LN1 out
__device__ float g_fused[(size_t)BATCH*1024*HW];  // pin out (2*DIM=1024 ch)
__device__ float g_dw  [(size_t)BATCH*DWC *HW];   // depthwise out (+bias)
__device__ float g_y0  [(size_t)BATCH* 32 *HW];
__device__ float g_y1  [(size_t)BATCH* 64 *HW];
__device__ float g_y2  [(size_t)BATCH*128 *HW];
__device__ float g_y3  [(size_t)BATCH*256 *HW];
__device__ float g_y4  [(size_t)BATCH*512 *HW];
__device__ float g_x1  [(size_t)BATCH*DIM *HW];   // x + g1*gnconv(x)
__device__ float g_ln2 [(size_t)BATCH*DIM *HW];   // LN2 out
__device__ float g_h   [(size_t)BATCH*2048*HW];   // fc1+gelu out

// ---------------- LayerNorm over channel dim (NCHW) ----------------
__global__ __launch_bounds__(256) void ln_kernel(
    const float* __restrict__ x, const float* __restrict__ w,
    const float* __restrict__ b, float* __restrict__ out)
{
    int bi  = blockIdx.x >> 5;
    int px0 = (blockIdx.x & 31) << 5;
    int tx = threadIdx.x;
    int ty = threadIdx.y;
    const float* xb = x + (size_t)bi*DIM*HW + px0 + tx;

    float s = 0.f, ss = 0.f;
    for (int c = ty; c < DIM; c += 8) {
        float v = xb[(size_t)c*HW];
        s += v; ss += v*v;
    }
    __shared__ float Ss[8][32], Sq[8][32];
    Ss[ty][tx] = s; Sq[ty][tx] = ss;
    __syncthreads();
    if (ty == 0) {
        float a = 0.f, q = 0.f;
        #pragma unroll
        for (int i = 0; i < 8; i++) { a += Ss[i][tx]; q += Sq[i][tx]; }
        float mean = a * (1.0f/DIM);
        float var  = q * (1.0f/DIM) - mean*mean;
        Ss[0][tx] = mean;
        Sq[0][tx] = rsqrtf(var + 1e-6f);
    }
    __syncthreads();
    float mean = Ss[0][tx], inv = Sq[0][tx];
    float* ob = out + (size_t)bi*DIM*HW + px0 + tx;
    for (int c = ty; c < DIM; c += 8) {
        float v = xb[(size_t)c*HW];
        ob[(size_t)c*HW] = w[c] * ((v - mean) * inv) + b[c];
    }
}

// -------- 7x7 depthwise conv (pad 3) on abc = fused[:, 32:1024] --------
__global__ __launch_bounds__(256) void dwconv_kernel(
    const float* __restrict__ fused, const float* __restrict__ w,
    const float* __restrict__ bias, float* __restrict__ out)
{
    int ch = blockIdx.x;
    int bi = blockIdx.y;
    const float* ip = fused + ((size_t)bi*1024 + 32 + ch) * HW;
    __shared__ float tile[38][38];
    __shared__ float kw[49];
    int tid = threadIdx.x;
    if (tid < 49) kw[tid] = w[(size_t)ch*49 + tid];
    for (int i = tid; i < 38*38; i += 256) {
        int r = i / 38 - 3, c = i % 38 - 3;
        tile[i/38][i%38] = (r >= 0 && r < 32 && c >= 0 && c < 32) ? ip[r*32 + c] : 0.f;
    }
    __syncthreads();
    float bv = bias[ch];
    float* op = out + ((size_t)bi*DWC + ch) * HW;
    for (int i = tid; i < 1024; i += 256) {
        int r = i >> 5, c = i & 31;
        float acc = bv;
        #pragma unroll
        for (int kr = 0; kr < 7; kr++)
            #pragma unroll
            for (int kc = 0; kc < 7; kc++)
                acc += tile[r+kr][c+kc] * kw[kr*7 + kc];
        op[i] = acc;
    }
}

// -------- y0 = pwa * dw_list[0] --------
__global__ __launch_bounds__(256) void gate0_kernel(
    const float* __restrict__ fused, const float* __restrict__ dw,
    float* __restrict__ y0)
{
    size_t i = (size_t)blockIdx.x * 256 + threadIdx.x;
    size_t bi = i / (32*HW);
    size_t r  = i % (32*HW);
    y0[i] = fused[bi*(size_t)1024*HW + r] * dw[bi*(size_t)DWC*HW + r];
}

// ================= bf16 tensor-core GEMM =================
// out[b] = W(MxK) @ X[b](KxN) + bias, N = 1024.
// fp32 in gmem; converted to bf16 at smem store. Block 64x128x32, 8 warps (2x4),
// warp tile 32x32, mma.m16n8k16. Epilogue: gate / gelu / residual fused.
__global__ __launch_bounds__(256) void gemm_bf16_kernel(
    const float* __restrict__ W, const float* __restrict__ X,
    const float* __restrict__ bias, float* __restrict__ out,
    int M, int K,
    const float* __restrict__ gate, int gate_chofs,
    const float* __restrict__ resid, const float* __restrict__ gvec,
    int do_gelu)
{
    __shared__ __nv_bfloat16 As[64 * 40];   // 64 rows x (32+8 pad)
    __shared__ __nv_bfloat16 Bs[32 * 136];  // 32 rows x (128+8 pad)

    const int tid  = threadIdx.x;
    const int lane = tid & 31;
    const int wid  = tid >> 5;
    const int warp_m = wid >> 2;   // 0..1 -> 32 rows
    const int warp_n = wid & 3;    // 0..3 -> 32 cols

    const int bi = blockIdx.z;
    const int m0 = blockIdx.y * 64;
    const int n0 = blockIdx.x * 128;
    const float* Xb = X + (size_t)bi * K * NPIX;
    float* Ob = out + (size_t)bi * M * NPIX;

    // gmem load assignments
    const int ar = tid >> 2, ac = (tid & 3) * 8;     // A: 64 rows x 8 floats
    const int br = tid >> 3, bc = (tid & 7) * 16;    // B: 32 rows x 16 floats
    const float* Ap = W  + (size_t)(m0 + ar) * K + ac;
    const float* Bp = Xb + (size_t)br * NPIX + n0 + bc;

    __nv_bfloat162* As2 = (__nv_bfloat162*)(As + ar * 40 + ac);
    __nv_bfloat162* Bs2 = (__nv_bfloat162*)(Bs + br * 136 + bc);

    // ldmatrix shared addresses
    uint32_t As_sh = (uint32_t)__cvta_generic_to_shared(As);
    uint32_t Bs_sh = (uint32_t)__cvta_generic_to_shared(Bs);
    const int lrow = lane & 15;
    const int lc8  = (lane >> 4) << 3;
    uint32_t a_base = As_sh + ((warp_m * 32 + lrow) * 40 + lc8) * 2;
    uint32_t b_base = Bs_sh + (lrow * 136 + warp_n * 32 + lc8) * 2;

    float acc[2][4][4];
    #pragma unroll
    for (int i = 0; i < 2; i++)
        #pragma unroll
        for (int j = 0; j < 4; j++)
            #pragma unroll
            for (int k = 0; k < 4; k++) acc[i][j][k] = 0.f;

    const int KT = K >> 5;
    float4 fa0, fa1, fb0, fb1, fb2, fb3;

    // prologue load tile 0
    fa0 = *(const float4*)(Ap);
    fa1 = *(const float4*)(Ap + 4);
    fb0 = *(const float4*)(Bp);
    fb1 = *(const float4*)(Bp + 4);
    fb2 = *(const float4*)(Bp + 8);
    fb3 = *(const float4*)(Bp + 12);
    As2[0] = __floats2bfloat162_rn(fa0.x, fa0.y);
    As2[1] = __floats2bfloat162_rn(fa0.z, fa0.w);
    As2[2] = __floats2bfloat162_rn(fa1.x, fa1.y);
    As2[3] = __floats2bfloat162_rn(fa1.z, fa1.w);
    Bs2[0] = __floats2bfloat162_rn(fb0.x, fb0.y);
    Bs2[1] = __floats2bfloat162_rn(fb0.z, fb0.w);
    Bs2[2] = __floats2bfloat162_rn(fb1.x, fb1.y);
    Bs2[3] = __floats2bfloat162_rn(fb1.z, fb1.w);
    Bs2[4] = __floats2bfloat162_rn(fb2.x, fb2.y);
    Bs2[5] = __floats2bfloat162_rn(fb2.z, fb2.w);
    Bs2[6] = __floats2bfloat162_rn(fb3.x, fb3.y);
    Bs2[7] = __floats2bfloat162_rn(fb3.z, fb3.w);
    __syncthreads();

    for (int kt = 0; kt < KT; kt++) {
        const bool more = (kt + 1) < KT;
        if (more) {
            int k0 = (kt + 1) << 5;
            fa0 = *(const float4*)(Ap + k0);
            fa1 = *(const float4*)(Ap + k0 + 4);
            const float* bp = Bp + (size_t)k0 * NPIX;
            fb0 = *(const float4*)(bp);
            fb1 = *(const float4*)(bp + 4);
            fb2 = *(const float4*)(bp + 8);
            fb3 = *(const float4*)(bp + 12);
        }

        #pragma unroll
        for (int s = 0; s < 2; s++) {
            uint32_t ra[2][4], rb[2][4];
            #pragma unroll
            for (int mt = 0; mt < 2; mt++) {
                uint32_t addr = a_base + (mt * 16 * 40 + s * 16) * 2;
                asm volatile(
                    "ldmatrix.sync.aligned.m8n8.x4.shared.b16 {%0,%1,%2,%3}, [%4];"
                    : "=r"(ra[mt][0]), "=r"(ra[mt][1]), "=r"(ra[mt][2]), "=r"(ra[mt][3])
                    : "r"(addr));
            }
            #pragma unroll
            for (int nt = 0; nt < 2; nt++) {
                uint32_t addr = b_base + (s * 16 * 136 + nt * 16) * 2;
                asm volatile(
                    "ldmatrix.sync.aligned.m8n8.x4.trans.shared.b16 {%0,%1,%2,%3}, [%4];"
                    : "=r"(rb[nt][0]), "=r"(rb[nt][1]), "=r"(rb[nt][2]), "=r"(rb[nt][3])
                    : "r"(addr));
            }
            #pragma unroll
            for (int mt = 0; mt < 2; mt++) {
                #pragma unroll
                for (int nf = 0; nf < 4; nf++) {
                    uint32_t b0 = rb[nf >> 1][(nf & 1) * 2 + 0];
                    uint32_t b1 = rb[nf >> 1][(nf & 1) * 2 + 1];
                    asm volatile(
                        "mma.sync.aligned.m16n8k16.row.col.f32.bf16.bf16.f32 "
                        "{%0,%1,%2,%3}, {%4,%5,%6,%7}, {%8,%9}, {%0,%1,%2,%3};"
                        : "+f"(acc[mt][nf][0]), "+f"(acc[mt][nf][1]),
                          "+f"(acc[mt][nf][2]), "+f"(acc[mt][nf][3])
                        : "r"(ra[mt][0]), "r"(ra[mt][1]), "r"(ra[mt][2]), "r"(ra[mt][3]),
                          "r"(b0), "r"(b1));
                }
            }
        }
        __syncthreads();
        if (more) {
            As2[0] = __floats2bfloat162_rn(fa0.x, fa0.y);
            As2[1] = __floats2bfloat162_rn(fa0.z, fa0.w);
            As2[2] = __floats2bfloat162_rn(fa1.x, fa1.y);
            As2[3] = __floats2bfloat162_rn(fa1.z, fa1.w);
            Bs2[0] = __floats2bfloat162_rn(fb0.x, fb0.y);
            Bs2[1] = __floats2bfloat162_rn(fb0.z, fb0.w);
            Bs2[2] = __floats2bfloat162_rn(fb1.x, fb1.y);
            Bs2[3] = __floats2bfloat162_rn(fb1.z, fb1.w);
            Bs2[4] = __floats2bfloat162_rn(fb2.x, fb2.y);
            Bs2[5] = __floats2bfloat162_rn(fb2.z, fb2.w);
            Bs2[6] = __floats2bfloat162_rn(fb3.x, fb3.y);
            Bs2[7] = __floats2bfloat162_rn(fb3.z, fb3.w);
            __syncthreads();
        }
    }

    // epilogue
    const int row  = lane >> 2;
    const int colp = (lane & 3) * 2;
    #pragma unroll
    for (int mt = 0; mt < 2; mt++) {
        #pragma unroll
        for (int nf = 0; nf < 4; nf++) {
            int n = n0 + warp_n * 32 + nf * 8 + colp;
            #pragma unroll
            for (int half = 0; half < 2; half++) {
                int m = m0 + warp_m * 32 + mt * 16 + row + half * 8;
                float v0 = acc[mt][nf][half * 2 + 0];
                float v1 = acc[mt][nf][half * 2 + 1];
                float bval = bias[m];
                v0 += bval; v1 += bval;
                if (gate) {
                    const float* gp = gate + ((size_t)bi * DWC + gate_chofs + m) * NPIX + n;
                    v0 *= gp[0]; v1 *= gp[1];
                }
                if (do_gelu) {
                    v0 = 0.5f * v0 * (1.0f + erff(v0 * 0.70710678118654752f));
                    v1 = 0.5f * v1 * (1.0f + erff(v1 * 0.70710678118654752f));
                }
                if (resid) {
                    const float* rp = resid + ((size_t)bi * M + m) * NPIX + n;
                    float gm = gvec[m];
                    v0 = rp[0] + gm * v0;
                    v1 = rp[1] + gm * v1;
                }
                float2 p; p.x = v0; p.y = v1;
                *(float2*)&Ob[(size_t)m * NPIX + n] = p;
            }
        }
    }
}

// ---------------- host launch ----------------
extern "C" void kernel_launch(void* const* d_in, const int* in_sizes, int n_in,
                              void* d_out, int out_size)
{
    (void)in_sizes; (void)n_in; (void)out_size;
    const float* x      = (const float*)d_in[0];
    const float* ln1_w  = (const float*)d_in[1];
    const float* ln1_b  = (const float*)d_in[2];
    const float* pin_w  = (const float*)d_in[3];
    const float* pin_b  = (const float*)d_in[4];
    const float* dw_w   = (const float*)d_in[5];
    const float* dw_b   = (const float*)d_in[6];
    const float* pw0_w  = (const float*)d_in[7];
    const float* pw0_b  = (const float*)d_in[8];
    const float* pw1_w  = (const float*)d_in[9];
    const float* pw1_b  = (const float*)d_in[10];
    const float* pw2_w  = (const float*)d_in[11];
    const float* pw2_b  = (const float*)d_in[12];
    const float* pw3_w  = (const float*)d_in[13];
    const float* pw3_b  = (const float*)d_in[14];
    const float* pout_w = (const float*)d_in[15];
    const float* pout_b = (const float*)d_in[16];
    const float* ln2_w  = (const float*)d_in[17];
    const float* ln2_b  = (const float*)d_in[18];
    const float* fc1_w  = (const float*)d_in[19];
    const float* fc1_b  = (const float*)d_in[20];
    const float* fc2_w  = (const float*)d_in[21];
    const float* fc2_b  = (const float*)d_in[22];
    const float* g1     = (const float*)d_in[23];
    const float* g2     = (const float*)d_in[24];
    float* out = (float*)d_out;

    float *p_ln, *p_fused, *p_dw, *p_y0, *p_y1, *p_y2, *p_y3, *p_y4, *p_x1, *p_ln2, *p_h;
    cudaGetSymbolAddress((void**)&p_ln,    g_ln);
    cudaGetSymbolAddress((void**)&p_fused, g_fused);
    cudaGetSymbolAddress((void**)&p_dw,    g_dw);
    cudaGetSymbolAddress((void**)&p_y0,    g_y0);
    cudaGetSymbolAddress((void**)&p_y1,    g_y1);
    cudaGetSymbolAddress((void**)&p_y2,    g_y2);
    cudaGetSymbolAddress((void**)&p_y3,    g_y3);
    cudaGetSymbolAddress((void**)&p_y4,    g_y4);
    cudaGetSymbolAddress((void**)&p_x1,    g_x1);
    cudaGetSymbolAddress((void**)&p_ln2,   g_ln2);
    cudaGetSymbolAddress((void**)&p_h,     g_h);

    dim3 lnBlock(32, 8);

    // 1) LN1
    ln_kernel<<<BATCH*32, lnBlock>>>(x, ln1_w, ln1_b, p_ln);
    // 2) pin: fused = pin_w(1024x512) @ ln1
    gemm_bf16_kernel<<<dim3(8,16,BATCH), 256>>>(pin_w, p_ln, pin_b, p_fused, 1024, 512,
                                                nullptr, 0, nullptr, nullptr, 0);
    // 3) depthwise 7x7 on abc (+bias)
    dwconv_kernel<<<dim3(DWC, BATCH), 256>>>(p_fused, dw_w, dw_b, p_dw);
    // 4) y0 = pwa * dw[0:32]
    gate0_kernel<<<(BATCH*32*HW)/256, 256>>>(p_fused, p_dw, p_y0);
    // 5..8) gating chain
    gemm_bf16_kernel<<<dim3(8,1,BATCH), 256>>>(pw0_w, p_y0, pw0_b, p_y1,  64,  32,
                                               p_dw,  32, nullptr, nullptr, 0);
    gemm_bf16_kernel<<<dim3(8,2,BATCH), 256>>>(pw1_w, p_y1, pw1_b, p_y2, 128,  64,
                                               p_dw,  96, nullptr, nullptr, 0);
    gemm_bf16_kernel<<<dim3(8,4,BATCH), 256>>>(pw2_w, p_y2, pw2_b, p_y3, 256, 128,
                                               p_dw, 224, nullptr, nullptr, 0);
    gemm_bf16_kernel<<<dim3(8,8,BATCH), 256>>>(pw3_w, p_y3, pw3_b, p_y4, 512, 256,
                                               p_dw, 480, nullptr, nullptr, 0);
    // 9) pout + first residual
    gemm_bf16_kernel<<<dim3(8,8,BATCH), 256>>>(pout_w, p_y4, pout_b, p_x1, 512, 512,
                                               nullptr, 0, x, g1, 0);
    // 10) LN2
    ln_kernel<<<BATCH*32, lnBlock>>>(p_x1, ln2_w, ln2_b, p_ln2);
    // 11) fc1 + exact GELU
    gemm_bf16_kernel<<<dim3(8,32,BATCH), 256>>>(fc1_w, p_ln2, fc1_b, p_h, 2048, 512,
                                                nullptr, 0, nullptr, nullptr, 1);
    // 12) fc2 + second residual -> out
    gemm_bf16_kernel<<<dim3(8,8,BATCH), 256>>>(fc2_w, p_h, fc2_b, out, 512, 2048,
                                               nullptr, 0, p_x1, g2, 0);
}

// round 5
// speedup vs baseline: 4.3547x; 1.7103x over previous
#include <cuda_runtime.h>
#include <cuda_bf16.h>
#include <math.h>
#include <stddef.h>
#include <stdint.h>

#define BATCH 16
#define DIM   512
#define HW    1024
#define NPIX  1024
#define DWC   992

typedef __nv_bfloat16 bf16;

// -------- scratch (device globals) --------
__device__ bf16  g_lnb [(size_t)BATCH*DIM *HW];
__device__ bf16  g_fusedb[(size_t)BATCH*1024*HW];
__device__ bf16  g_dwb [(size_t)BATCH*DWC *HW];
__device__ bf16  g_y0b [(size_t)BATCH* 32 *HW];
__device__ bf16  g_y1b [(size_t)BATCH* 64 *HW];
__device__ bf16  g_y2b [(size_t)BATCH*128 *HW];
__device__ bf16  g_y3b [(size_t)BATCH*256 *HW];
__device__ bf16  g_y4b [(size_t)BATCH*512 *HW];
__device__ float g_x1  [(size_t)BATCH*DIM *HW];
__device__ bf16  g_ln2b[(size_t)BATCH*DIM *HW];
__device__ bf16  g_hb  [(size_t)BATCH*2048*HW];
// bf16 weights
__device__ bf16  g_wpin[1024*512];
__device__ bf16  g_wpw0[64*32];
__device__ bf16  g_wpw1[128*64];
__device__ bf16  g_wpw2[256*128];
__device__ bf16  g_wpw3[512*256];
__device__ bf16  g_wpout[512*512];
__device__ bf16  g_wfc1[2048*512];
__device__ bf16  g_wfc2[512*2048];

__device__ __forceinline__ uint32_t smem_u32(const void* p) {
    uint32_t a;
    asm("{ .reg .u64 t; cvta.to.shared.u64 t, %1; cvt.u32.u64 %0, t; }" : "=r"(a) : "l"(p));
    return a;
}
#define CP16(d, s) asm volatile("cp.async.cg.shared.global [%0], [%1], 16;" :: "r"(d), "l"(s) : "memory")
#define CP_COMMIT() asm volatile("cp.async.commit_group;" ::: "memory")
#define CP_WAIT0()  asm volatile("cp.async.wait_group 0;" ::: "memory")
#define CP_WAIT1()  asm volatile("cp.async.wait_group 1;" ::: "memory")

// ================= bf16 mma.sync GEMM =================
// out[b] = W(MxK) @ X[b](KxN=1024) + bias. Block tile 128x128, k-chunk 32,
// 8 warps (4m x 2n), warp tile 32x64. cp.async double-buffered, bf16 gmem operands.
__global__ __launch_bounds__(256) void gemm_bf16_kernel(
    const bf16* __restrict__ W, const bf16* __restrict__ X,
    const float* __restrict__ bias, void* __restrict__ out,
    int M, int K,
    const bf16* __restrict__ gate, int gate_chofs,
    const float* __restrict__ resid, const float* __restrict__ gvec,
    int do_gelu, int out_bf16)
{
    __shared__ bf16 As[2][128 * 40];   // 128 rows x (32 + 8 pad)
    __shared__ bf16 Bs[2][32 * 136];   // 32 rows x (128 + 8 pad)

    const int tid  = threadIdx.x;
    const int lane = tid & 31;
    const int wid  = tid >> 5;
    const int warp_m = wid >> 1;    // 0..3 -> 32-row tile
    const int warp_n = wid & 1;     // 0..1 -> 64-col tile

    const int bi = blockIdx.z;
    const int m0 = blockIdx.y * 128;
    const int n0 = blockIdx.x * 128;
    const bf16* Xb = X + (size_t)bi * K * NPIX;

    const uint32_t As_sh0 = smem_u32(As[0]);
    const uint32_t As_sh1 = smem_u32(As[1]);
    const uint32_t Bs_sh0 = smem_u32(Bs[0]);
    const uint32_t Bs_sh1 = smem_u32(Bs[1]);

    auto load_chunk = [&](int kc, int st) {
        uint32_t a_s = st ? As_sh1 : As_sh0;
        uint32_t b_s = st ? Bs_sh1 : Bs_sh0;
        // A: 128 rows x 32 bf16 = 4 x 16B chunks per row -> 512 transfers
        #pragma unroll
        for (int i = 0; i < 2; i++) {
            int idx = tid + i * 256;
            int r = idx >> 2, c8 = idx & 3;
            int mr = m0 + r; if (mr >= M) mr = M - 1;
            CP16(a_s + (uint32_t)(r * 40 + c8 * 8) * 2,
                 W + (size_t)mr * K + kc * 32 + c8 * 8);
        }
        // B: 32 rows x 128 bf16 = 16 x 16B chunks per row -> 512 transfers
        #pragma unroll
        for (int i = 0; i < 2; i++) {
            int idx = tid + i * 256;
            int kr = idx >> 4, c = idx & 15;
            CP16(b_s + (uint32_t)(kr * 136 + c * 8) * 2,
                 Xb + (size_t)(kc * 32 + kr) * NPIX + n0 + c * 8);
        }
    };

    const int lrow = lane & 15;
    const int lc8  = (lane >> 4) << 3;

    float acc[2][8][4];
    #pragma unroll
    for (int i = 0; i < 2; i++)
        #pragma unroll
        for (int j = 0; j < 8; j++)
            #pragma unroll
            for (int k = 0; k < 4; k++) acc[i][j][k] = 0.f;

    const int KT = K >> 5;

    load_chunk(0, 0);
    CP_COMMIT();

    for (int kt = 0; kt < KT; kt++) {
        if (kt + 1 < KT) {
            load_chunk(kt + 1, (kt + 1) & 1);
            CP_COMMIT();
            CP_WAIT1();
        } else {
            CP_WAIT0();
        }
        __syncthreads();

        const int st = kt & 1;
        uint32_t a_base = (st ? As_sh1 : As_sh0) + ((warp_m * 32 + lrow) * 40 + lc8) * 2;
        uint32_t b_base = (st ? Bs_sh1 : Bs_sh0) + (lrow * 136 + warp_n * 64 + lc8) * 2;

        #pragma unroll
        for (int s = 0; s < 2; s++) {
            uint32_t ra[2][4], rb[4][4];
            #pragma unroll
            for (int mt = 0; mt < 2; mt++) {
                uint32_t addr = a_base + (mt * 16 * 40 + s * 16) * 2;
                asm volatile(
                    "ldmatrix.sync.aligned.m8n8.x4.shared.b16 {%0,%1,%2,%3}, [%4];"
                    : "=r"(ra[mt][0]), "=r"(ra[mt][1]), "=r"(ra[mt][2]), "=r"(ra[mt][3])
                    : "r"(addr));
            }
            #pragma unroll
            for (int nt = 0; nt < 4; nt++) {
                uint32_t addr = b_base + (s * 16 * 136 + nt * 16) * 2;
                asm volatile(
                    "ldmatrix.sync.aligned.m8n8.x4.trans.shared.b16 {%0,%1,%2,%3}, [%4];"
                    : "=r"(rb[nt][0]), "=r"(rb[nt][1]), "=r"(rb[nt][2]), "=r"(rb[nt][3])
                    : "r"(addr));
            }
            #pragma unroll
            for (int mt = 0; mt < 2; mt++) {
                #pragma unroll
                for (int nf = 0; nf < 8; nf++) {
                    uint32_t b0 = rb[nf >> 1][(nf & 1) * 2 + 0];
                    uint32_t b1 = rb[nf >> 1][(nf & 1) * 2 + 1];
                    asm volatile(
                        "mma.sync.aligned.m16n8k16.row.col.f32.bf16.bf16.f32 "
                        "{%0,%1,%2,%3}, {%4,%5,%6,%7}, {%8,%9}, {%0,%1,%2,%3};"
                        : "+f"(acc[mt][nf][0]), "+f"(acc[mt][nf][1]),
                          "+f"(acc[mt][nf][2]), "+f"(acc[mt][nf][3])
                        : "r"(ra[mt][0]), "r"(ra[mt][1]), "r"(ra[mt][2]), "r"(ra[mt][3]),
                          "r"(b0), "r"(b1));
                }
            }
        }
        __syncthreads();
    }

    // ---- epilogue ----
    const int row  = lane >> 2;
    const int colp = (lane & 3) * 2;
    #pragma unroll
    for (int mt = 0; mt < 2; mt++) {
        #pragma unroll
        for (int nf = 0; nf < 8; nf++) {
            int n = n0 + warp_n * 64 + nf * 8 + colp;
            #pragma unroll
            for (int half = 0; half < 2; half++) {
                int m = m0 + warp_m * 32 + mt * 16 + row + half * 8;
                if (m >= M) continue;
                float v0 = acc[mt][nf][half * 2 + 0];
                float v1 = acc[mt][nf][half * 2 + 1];
                float bval = bias[m];
                v0 += bval; v1 += bval;
                if (gate) {
                    const bf16* gp = gate + ((size_t)bi * DWC + gate_chofs + m) * NPIX + n;
                    v0 *= __bfloat162float(gp[0]);
                    v1 *= __bfloat162float(gp[1]);
                }
                if (do_gelu) {
                    v0 = 0.5f * v0 * (1.0f + erff(v0 * 0.70710678118654752f));
                    v1 = 0.5f * v1 * (1.0f + erff(v1 * 0.70710678118654752f));
                }
                if (resid) {
                    const float* rp = resid + ((size_t)bi * M + m) * NPIX + n;
                    float gm = gvec[m];
                    v0 = rp[0] + gm * v0;
                    v1 = rp[1] + gm * v1;
                }
                if (out_bf16) {
                    __nv_bfloat162* op = (__nv_bfloat162*)((bf16*)out + ((size_t)bi * M + m) * NPIX + n);
                    *op = __floats2bfloat162_rn(v0, v1);
                } else {
                    float2 p; p.x = v0; p.y = v1;
                    *(float2*)((float*)out + ((size_t)bi * M + m) * NPIX + n) = p;
                }
            }
        }
    }
}

// ---------------- weight fp32 -> bf16 ----------------
__global__ __launch_bounds__(256) void conv_w(const float* __restrict__ s,
                                              bf16* __restrict__ d, int n)
{
    for (int i = blockIdx.x * 256 + threadIdx.x; i < n; i += gridDim.x * 256)
        d[i] = __float2bfloat16(s[i]);
}

// ---------------- LayerNorm (channel dim, NCHW), bf16 out ----------------
__global__ __launch_bounds__(256) void ln_kernel(
    const float* __restrict__ x, const float* __restrict__ w,
    const float* __restrict__ b, bf16* __restrict__ out)
{
    int bi  = blockIdx.x >> 5;
    int px0 = (blockIdx.x & 31) << 5;
    int tx = threadIdx.x, ty = threadIdx.y;
    const float* xb = x + (size_t)bi * DIM * HW + px0 + tx;

    float s = 0.f, ss = 0.f;
    for (int c = ty; c < DIM; c += 8) {
        float v = xb[(size_t)c * HW];
        s += v; ss += v * v;
    }
    __shared__ float Ss[8][32], Sq[8][32];
    Ss[ty][tx] = s; Sq[ty][tx] = ss;
    __syncthreads();
    if (ty == 0) {
        float a = 0.f, q = 0.f;
        #pragma unroll
        for (int i = 0; i < 8; i++) { a += Ss[i][tx]; q += Sq[i][tx]; }
        float mean = a * (1.0f / DIM);
        float var  = q * (1.0f / DIM) - mean * mean;
        Ss[0][tx] = mean;
        Sq[0][tx] = rsqrtf(var + 1e-6f);
    }
    __syncthreads();
    float mean = Ss[0][tx], inv = Sq[0][tx];
    bf16* ob = out + (size_t)bi * DIM * HW + px0 + tx;
    for (int c = ty; c < DIM; c += 8) {
        float v = xb[(size_t)c * HW];
        ob[(size_t)c * HW] = __float2bfloat16(w[c] * ((v - mean) * inv) + b[c]);
    }
}

// ---------------- 7x7 depthwise conv, bf16 in/out ----------------
__global__ __launch_bounds__(256) void dwconv_kernel(
    const bf16* __restrict__ fused, const float* __restrict__ w,
    const float* __restrict__ bias, bf16* __restrict__ out)
{
    int ch = blockIdx.x, bi = blockIdx.y;
    const bf16* ip = fused + ((size_t)bi * 1024 + 32 + ch) * HW;
    __shared__ float tile[38][38];
    __shared__ float kw[49];
    int tid = threadIdx.x;
    if (tid < 49) kw[tid] = w[(size_t)ch * 49 + tid];
    for (int i = tid; i < 38 * 38; i += 256) {
        int r = i / 38 - 3, c = i % 38 - 3;
        tile[i / 38][i % 38] = (r >= 0 && r < 32 && c >= 0 && c < 32)
            ? __bfloat162float(ip[r * 32 + c]) : 0.f;
    }
    __syncthreads();
    float bv = bias[ch];
    bf16* op = out + ((size_t)bi * DWC + ch) * HW;
    for (int i = tid; i < 1024; i += 256) {
        int r = i >> 5, c = i & 31;
        float acc = bv;
        #pragma unroll
        for (int kr = 0; kr < 7; kr++)
            #pragma unroll
            for (int kc = 0; kc < 7; kc++)
                acc += tile[r + kr][c + kc] * kw[kr * 7 + kc];
        op[i] = __float2bfloat16(acc);
    }
}

// -------- y0 = pwa * dw_list[0] --------
__global__ __launch_bounds__(256) void gate0_kernel(
    const bf16* __restrict__ fused, const bf16* __restrict__ dw,
    bf16* __restrict__ y0)
{
    size_t i = (size_t)blockIdx.x * 256 + threadIdx.x;
    size_t bi = i / (32 * HW);
    size_t r  = i % (32 * HW);
    float v = __bfloat162float(fused[bi * (size_t)1024 * HW + r]) *
              __bfloat162float(dw[bi * (size_t)DWC * HW + r]);
    y0[i] = __float2bfloat16(v);
}

// ---------------- host launch ----------------
static void launch_gemm(const bf16* W, const bf16* X, const float* bias, void* out,
                        int M, int K, const bf16* gate, int chofs,
                        const float* resid, const float* gvec, int gelu, int obf)
{
    gemm_bf16_kernel<<<dim3(8, (M + 127) / 128, BATCH), 256>>>(
        W, X, bias, out, M, K, gate, chofs, resid, gvec, gelu, obf);
}

extern "C" void kernel_launch(void* const* d_in, const int* in_sizes, int n_in,
                              void* d_out, int out_size)
{
    (void)in_sizes; (void)n_in; (void)out_size;
    const float* x      = (const float*)d_in[0];
    const float* ln1_w  = (const float*)d_in[1];
    const float* ln1_b  = (const float*)d_in[2];
    const float* pin_w  = (const float*)d_in[3];
    const float* pin_b  = (const float*)d_in[4];
    const float* dw_w   = (const float*)d_in[5];
    const float* dw_b   = (const float*)d_in[6];
    const float* pw0_w  = (const float*)d_in[7];
    const float* pw0_b  = (const float*)d_in[8];
    const float* pw1_w  = (const float*)d_in[9];
    const float* pw1_b  = (const float*)d_in[10];
    const float* pw2_w  = (const float*)d_in[11];
    const float* pw2_b  = (const float*)d_in[12];
    const float* pw3_w  = (const float*)d_in[13];
    const float* pw3_b  = (const float*)d_in[14];
    const float* pout_w = (const float*)d_in[15];
    const float* pout_b = (const float*)d_in[16];
    const float* ln2_w  = (const float*)d_in[17];
    const float* ln2_b  = (const float*)d_in[18];
    const float* fc1_w  = (const float*)d_in[19];
    const float* fc1_b  = (const float*)d_in[20];
    const float* fc2_w  = (const float*)d_in[21];
    const float* fc2_b  = (const float*)d_in[22];
    const float* g1     = (const float*)d_in[23];
    const float* g2     = (const float*)d_in[24];
    float* out = (float*)d_out;

    bf16 *p_lnb, *p_fusedb, *p_dwb, *p_y0b, *p_y1b, *p_y2b, *p_y3b, *p_y4b, *p_ln2b, *p_hb;
    bf16 *w_pin, *w_pw0, *w_pw1, *w_pw2, *w_pw3, *w_pout, *w_fc1, *w_fc2;
    float *p_x1;
    cudaGetSymbolAddress((void**)&p_lnb,   g_lnb);
    cudaGetSymbolAddress((void**)&p_fusedb,g_fusedb);
    cudaGetSymbolAddress((void**)&p_dwb,   g_dwb);
    cudaGetSymbolAddress((void**)&p_y0b,   g_y0b);
    cudaGetSymbolAddress((void**)&p_y1b,   g_y1b);
    cudaGetSymbolAddress((void**)&p_y2b,   g_y2b);
    cudaGetSymbolAddress((void**)&p_y3b,   g_y3b);
    cudaGetSymbolAddress((void**)&p_y4b,   g_y4b);
    cudaGetSymbolAddress((void**)&p_x1,    g_x1);
    cudaGetSymbolAddress((void**)&p_ln2b,  g_ln2b);
    cudaGetSymbolAddress((void**)&p_hb,    g_hb);
    cudaGetSymbolAddress((void**)&w_pin,   g_wpin);
    cudaGetSymbolAddress((void**)&w_pw0,   g_wpw0);
    cudaGetSymbolAddress((void**)&w_pw1,   g_wpw1);
    cudaGetSymbolAddress((void**)&w_pw2,   g_wpw2);
    cudaGetSymbolAddress((void**)&w_pw3,   g_wpw3);
    cudaGetSymbolAddress((void**)&w_pout,  g_wpout);
    cudaGetSymbolAddress((void**)&w_fc1,   g_wfc1);
    cudaGetSymbolAddress((void**)&w_fc2,   g_wfc2);

    // weight conversion (once per launch; cheap)
    conv_w<<<512, 256>>>(pin_w,  w_pin,  1024*512);
    conv_w<<<8,   256>>>(pw0_w,  w_pw0,  64*32);
    conv_w<<<32,  256>>>(pw1_w,  w_pw1,  128*64);
    conv_w<<<128, 256>>>(pw2_w,  w_pw2,  256*128);
    conv_w<<<512, 256>>>(pw3_w,  w_pw3,  512*256);
    conv_w<<<512, 256>>>(pout_w, w_pout, 512*512);
    conv_w<<<512, 256>>>(fc1_w,  w_fc1,  2048*512);
    conv_w<<<512, 256>>>(fc2_w,  w_fc2,  512*2048);

    dim3 lnBlock(32, 8);

    // 1) LN1 -> bf16
    ln_kernel<<<BATCH*32, lnBlock>>>(x, ln1_w, ln1_b, p_lnb);
    // 2) pin
    launch_gemm(w_pin, p_lnb, pin_b, p_fusedb, 1024, 512, nullptr, 0, nullptr, nullptr, 0, 1);
    // 3) dwconv
    dwconv_kernel<<<dim3(DWC, BATCH), 256>>>(p_fusedb, dw_w, dw_b, p_dwb);
    // 4) gate0
    gate0_kernel<<<(BATCH*32*HW)/256, 256>>>(p_fusedb, p_dwb, p_y0b);
    // 5..8) gating chain
    launch_gemm(w_pw0, p_y0b, pw0_b, p_y1b,  64,  32, p_dwb,  32, nullptr, nullptr, 0, 1);
    launch_gemm(w_pw1, p_y1b, pw1_b, p_y2b, 128,  64, p_dwb,  96, nullptr, nullptr, 0, 1);
    launch_gemm(w_pw2, p_y2b, pw2_b, p_y3b, 256, 128, p_dwb, 224, nullptr, nullptr, 0, 1);
    launch_gemm(w_pw3, p_y3b, pw3_b, p_y4b, 512, 256, p_dwb, 480, nullptr, nullptr, 0, 1);
    // 9) pout + residual -> x1 (fp32)
    launch_gemm(w_pout, p_y4b, pout_b, p_x1, 512, 512, nullptr, 0, x, g1, 0, 0);
    // 10) LN2 -> bf16
    ln_kernel<<<BATCH*32, lnBlock>>>(p_x1, ln2_w, ln2_b, p_ln2b);
    // 11) fc1 + GELU -> bf16
    launch_gemm(w_fc1, p_ln2b, fc1_b, p_hb, 2048, 512, nullptr, 0, nullptr, nullptr, 1, 1);
    // 12) fc2 + residual -> out (fp32)
    launch_gemm(w_fc2, p_hb, fc2_b, out, 512, 2048, nullptr, 0, p_x1, g2, 0, 0);
}

// round 7
// speedup vs baseline: 4.5249x; 1.0391x over previous
#include <cuda_runtime.h>
#include <cuda_bf16.h>
#include <math.h>
#include <stddef.h>
#include <stdint.h>

#define BATCH 16
#define DIM   512
#define HW    1024
#define NPIX  1024
#define DWC   992

typedef __nv_bfloat16 bf16;

// -------- scratch (device globals) --------
__device__ bf16  g_lnb [(size_t)BATCH*DIM *HW];
__device__ bf16  g_fusedb[(size_t)BATCH*1024*HW];
__device__ bf16  g_dwb [(size_t)BATCH*DWC *HW];
__device__ bf16  g_y0b [(size_t)BATCH* 32 *HW];
__device__ bf16  g_y1b [(size_t)BATCH* 64 *HW];
__device__ bf16  g_y2b [(size_t)BATCH*128 *HW];
__device__ bf16  g_y3b [(size_t)BATCH*256 *HW];
__device__ bf16  g_y4b [(size_t)BATCH*512 *HW];
__device__ float g_x1  [(size_t)BATCH*DIM *HW];
__device__ bf16  g_ln2b[(size_t)BATCH*DIM *HW];
__device__ bf16  g_hb  [(size_t)BATCH*2048*HW];
// bf16 weights
__device__ bf16  g_wpin[1024*512];
__device__ bf16  g_wpw0[64*32];
__device__ bf16  g_wpw1[128*64];
__device__ bf16  g_wpw2[256*128];
__device__ bf16  g_wpw3[512*256];
__device__ bf16  g_wpout[512*512];
__device__ bf16  g_wfc1[2048*512];
__device__ bf16  g_wfc2[512*2048];

__device__ __forceinline__ uint32_t smem_u32(const void* p) {
    uint32_t a;
    asm("{ .reg .u64 t; cvta.to.shared.u64 t, %1; cvt.u32.u64 %0, t; }" : "=r"(a) : "l"(p));
    return a;
}
#define CP16Z(d, s, sz) asm volatile("cp.async.cg.shared.global [%0], [%1], 16, %2;" :: "r"(d), "l"(s), "r"(sz) : "memory")
#define CP_COMMIT() asm volatile("cp.async.commit_group;" ::: "memory")
#define CP_WAIT0()  asm volatile("cp.async.wait_group 0;" ::: "memory")
#define CP_WAIT1()  asm volatile("cp.async.wait_group 1;" ::: "memory")

// smem geometry (elements): A stage 128x72, B stage 64x136
#define A_ROWSTRIDE 72
#define B_ROWSTRIDE 136
#define A_STAGE_B   (128 * A_ROWSTRIDE * 2)                 // 18432 bytes
#define STAGE_B     (A_STAGE_B + 64 * B_ROWSTRIDE * 2)      // 35840 bytes
#define GEMM_SMEM   (2 * STAGE_B)                           // 71680 bytes

// ================= bf16 mma.sync GEMM =================
// out[b] = W(MxK) @ X[b](KxN=1024) + bias. Block tile 128x128, k-chunk 64,
// 8 warps (4m x 2n), warp tile 32x64. cp.async double-buffered (dynamic smem).
__global__ __launch_bounds__(256, 2) void gemm_bf16_kernel(
    const bf16* __restrict__ W, const bf16* __restrict__ X,
    const float* __restrict__ bias, void* __restrict__ out,
    int M, int K,
    const bf16* __restrict__ gate, int gate_chofs,
    const float* __restrict__ resid, const float* __restrict__ gvec,
    int do_gelu, int out_bf16)
{
    extern __shared__ char dsm[];
    const uint32_t sb = smem_u32(dsm);

    const int tid  = threadIdx.x;
    const int lane = tid & 31;
    const int wid  = tid >> 5;
    const int warp_m = wid >> 1;    // 0..3 -> 32-row tile
    const int warp_n = wid & 1;     // 0..1 -> 64-col tile

    const int bi = blockIdx.z;
    const int m0 = blockIdx.y * 128;
    const int n0 = blockIdx.x * 128;
    const bf16* Xb = X + (size_t)bi * K * NPIX;

    auto load_chunk = [&](int kc, int st) {
        uint32_t a_s = sb + st * STAGE_B;
        uint32_t b_s = a_s + A_STAGE_B;
        int k0 = kc * 64;
        // A: 128 rows x 64 bf16 = 8 x 16B chunks per row -> 1024 transfers
        #pragma unroll
        for (int i = 0; i < 4; i++) {
            int idx = tid + i * 256;
            int r = idx >> 3, c8 = idx & 7;
            int mr = m0 + r; if (mr >= M) mr = M - 1;
            int kk = k0 + c8 * 8;
            int sz = (kk < K) ? 16 : 0;
            const bf16* src = W + (size_t)mr * K + (kk < K ? kk : 0);
            CP16Z(a_s + (uint32_t)(r * A_ROWSTRIDE + c8 * 8) * 2, src, sz);
        }
        // B: 64 rows x 128 bf16 = 16 x 16B chunks per row -> 1024 transfers
        #pragma unroll
        for (int i = 0; i < 4; i++) {
            int idx = tid + i * 256;
            int kr = idx >> 4, c = idx & 15;
            int kk = k0 + kr;
            int sz = (kk < K) ? 16 : 0;
            const bf16* src = Xb + (size_t)(kk < K ? kk : 0) * NPIX + n0 + c * 8;
            CP16Z(b_s + (uint32_t)(kr * B_ROWSTRIDE + c * 8) * 2, src, sz);
        }
    };

    const int lrow = lane & 15;
    const int lc8  = (lane >> 4) << 3;

    float acc[2][8][4];
    #pragma unroll
    for (int i = 0; i < 2; i++)
        #pragma unroll
        for (int j = 0; j < 8; j++)
            #pragma unroll
            for (int k = 0; k < 4; k++) acc[i][j][k] = 0.f;

    const int KT = (K + 63) >> 6;

    load_chunk(0, 0);
    CP_COMMIT();

    for (int kt = 0; kt < KT; kt++) {
        if (kt + 1 < KT) {
            load_chunk(kt + 1, (kt + 1) & 1);
            CP_COMMIT();
            CP_WAIT1();
        } else {
            CP_WAIT0();
        }
        __syncthreads();

        uint32_t a_s = sb + (kt & 1) * STAGE_B;
        uint32_t b_s = a_s + A_STAGE_B;
        uint32_t a_base = a_s + ((warp_m * 32 + lrow) * A_ROWSTRIDE + lc8) * 2;
        uint32_t b_base = b_s + (lrow * B_ROWSTRIDE + warp_n * 64 + lc8) * 2;

        #pragma unroll
        for (int s = 0; s < 4; s++) {
            uint32_t ra[2][4], rb[4][4];
            #pragma unroll
            for (int mt = 0; mt < 2; mt++) {
                uint32_t addr = a_base + (mt * 16 * A_ROWSTRIDE + s * 16) * 2;
                asm volatile(
                    "ldmatrix.sync.aligned.m8n8.x4.shared.b16 {%0,%1,%2,%3}, [%4];"
                    : "=r"(ra[mt][0]), "=r"(ra[mt][1]), "=r"(ra[mt][2]), "=r"(ra[mt][3])
                    : "r"(addr));
            }
            #pragma unroll
            for (int nt = 0; nt < 4; nt++) {
                uint32_t addr = b_base + (s * 16 * B_ROWSTRIDE + nt * 16) * 2;
                asm volatile(
                    "ldmatrix.sync.aligned.m8n8.x4.trans.shared.b16 {%0,%1,%2,%3}, [%4];"
                    : "=r"(rb[nt][0]), "=r"(rb[nt][1]), "=r"(rb[nt][2]), "=r"(rb[nt][3])
                    : "r"(addr));
            }
            #pragma unroll
            for (int mt = 0; mt < 2; mt++) {
                #pragma unroll
                for (int nf = 0; nf < 8; nf++) {
                    uint32_t b0 = rb[nf >> 1][(nf & 1) * 2 + 0];
                    uint32_t b1 = rb[nf >> 1][(nf & 1) * 2 + 1];
                    asm volatile(
                        "mma.sync.aligned.m16n8k16.row.col.f32.bf16.bf16.f32 "
                        "{%0,%1,%2,%3}, {%4,%5,%6,%7}, {%8,%9}, {%0,%1,%2,%3};"
                        : "+f"(acc[mt][nf][0]), "+f"(acc[mt][nf][1]),
                          "+f"(acc[mt][nf][2]), "+f"(acc[mt][nf][3])
                        : "r"(ra[mt][0]), "r"(ra[mt][1]), "r"(ra[mt][2]), "r"(ra[mt][3]),
                          "r"(b0), "r"(b1));
                }
            }
        }
        __syncthreads();
    }

    // ---- epilogue ----
    const int row  = lane >> 2;
    const int colp = (lane & 3) * 2;
    #pragma unroll
    for (int mt = 0; mt < 2; mt++) {
        #pragma unroll
        for (int nf = 0; nf < 8; nf++) {
            int n = n0 + warp_n * 64 + nf * 8 + colp;
            #pragma unroll
            for (int half = 0; half < 2; half++) {
                int m = m0 + warp_m * 32 + mt * 16 + row + half * 8;
                if (m >= M) continue;
                float v0 = acc[mt][nf][half * 2 + 0];
                float v1 = acc[mt][nf][half * 2 + 1];
                float bval = bias[m];
                v0 += bval; v1 += bval;
                if (gate) {
                    const bf16* gp = gate + ((size_t)bi * DWC + gate_chofs + m) * NPIX + n;
                    v0 *= __bfloat162float(gp[0]);
                    v1 *= __bfloat162float(gp[1]);
                }
                if (do_gelu) {
                    v0 = 0.5f * v0 * (1.0f + erff(v0 * 0.70710678118654752f));
                    v1 = 0.5f * v1 * (1.0f + erff(v1 * 0.70710678118654752f));
                }
                if (resid) {
                    const float* rp = resid + ((size_t)bi * M + m) * NPIX + n;
                    float gm = gvec[m];
                    v0 = rp[0] + gm * v0;
                    v1 = rp[1] + gm * v1;
                }
                if (out_bf16) {
                    __nv_bfloat162* op = (__nv_bfloat162*)((bf16*)out + ((size_t)bi * M + m) * NPIX + n);
                    *op = __floats2bfloat162_rn(v0, v1);
                } else {
                    float2 p; p.x = v0; p.y = v1;
                    *(float2*)((float*)out + ((size_t)bi * M + m) * NPIX + n) = p;
                }
            }
        }
    }
}

// ---------------- merged weight fp32 -> bf16 (single launch, float4) ----------------
__global__ __launch_bounds__(256) void conv_all(
    const float* s0, bf16* d0, const float* s1, bf16* d1,
    const float* s2, bf16* d2, const float* s3, bf16* d3,
    const float* s4, bf16* d4, const float* s5, bf16* d5,
    const float* s6, bf16* d6, const float* s7, bf16* d7)
{
    // element counts /4
    const int n4[8] = {131072, 512, 2048, 8192, 32768, 65536, 262144, 262144};
    const float* srcs[8] = {s0, s1, s2, s3, s4, s5, s6, s7};
    bf16* dsts[8] = {d0, d1, d2, d3, d4, d5, d6, d7};
    int total = 131072 + 512 + 2048 + 8192 + 32768 + 65536 + 262144 + 262144;
    for (int i = blockIdx.x * 256 + threadIdx.x; i < total; i += gridDim.x * 256) {
        int seg = 0, off = i;
        #pragma unroll
        for (int j = 0; j < 8; j++) {
            if (off >= n4[j]) { off -= n4[j]; seg = j + 1; }
            else break;
        }
        float4 v = ((const float4*)srcs[seg])[off];
        __nv_bfloat162* dp = (__nv_bfloat162*)dsts[seg] + off * 2;
        dp[0] = __floats2bfloat162_rn(v.x, v.y);
        dp[1] = __floats2bfloat162_rn(v.z, v.w);
    }
}

// ---------------- LayerNorm (channel dim, NCHW), bf16 out ----------------
__global__ __launch_bounds__(256) void ln_kernel(
    const float* __restrict__ x, const float* __restrict__ w,
    const float* __restrict__ b, bf16* __restrict__ out)
{
    int bi  = blockIdx.x >> 5;
    int px0 = (blockIdx.x & 31) << 5;
    int tx = threadIdx.x, ty = threadIdx.y;
    const float* xb = x + (size_t)bi * DIM * HW + px0 + tx;

    float s = 0.f, ss = 0.f;
    for (int c = ty; c < DIM; c += 8) {
        float v = xb[(size_t)c * HW];
        s += v; ss += v * v;
    }
    __shared__ float Ss[8][32], Sq[8][32];
    Ss[ty][tx] = s; Sq[ty][tx] = ss;
    __syncthreads();
    if (ty == 0) {
        float a = 0.f, q = 0.f;
        #pragma unroll
        for (int i = 0; i < 8; i++) { a += Ss[i][tx]; q += Sq[i][tx]; }
        float mean = a * (1.0f / DIM);
        float var  = q * (1.0f / DIM) - mean * mean;
        Ss[0][tx] = mean;
        Sq[0][tx] = rsqrtf(var + 1e-6f);
    }
    __syncthreads();
    float mean = Ss[0][tx], inv = Sq[0][tx];
    bf16* ob = out + (size_t)bi * DIM * HW + px0 + tx;
    for (int c = ty; c < DIM; c += 8) {
        float v = xb[(size_t)c * HW];
        ob[(size_t)c * HW] = __float2bfloat16(w[c] * ((v - mean) * inv) + b[c]);
    }
}

// ---------------- 7x7 depthwise conv (+ fused gate0 for ch<32) ----------------
__global__ __launch_bounds__(256) void dwconv_kernel(
    const bf16* __restrict__ fused, const float* __restrict__ w,
    const float* __restrict__ bias, bf16* __restrict__ out,
    bf16* __restrict__ y0)
{
    int ch = blockIdx.x, bi = blockIdx.y;
    const bf16* ip = fused + ((size_t)bi * 1024 + 32 + ch) * HW;
    __shared__ float tile[38][38];
    __shared__ float kw[49];
    int tid = threadIdx.x;
    if (tid < 49) kw[tid] = w[(size_t)ch * 49 + tid];
    for (int i = tid; i < 38 * 38; i += 256) {
        int r = i / 38 - 3, c = i % 38 - 3;
        tile[i / 38][i % 38] = (r >= 0 && r < 32 && c >= 0 && c < 32)
            ? __bfloat162float(ip[r * 32 + c]) : 0.f;
    }
    __syncthreads();
    float bv = bias[ch];
    bf16* op = out + ((size_t)bi * DWC + ch) * HW;
    const bf16* pwa = fused + ((size_t)bi * 1024 + ch) * HW;   // only used if ch<32
    bf16* y0p = y0 + ((size_t)bi * 32 + ch) * HW;
    for (int i = tid; i < 1024; i += 256) {
        int r = i >> 5, c = i & 31;
        float acc = bv;
        #pragma unroll
        for (int kr = 0; kr < 7; kr++)
            #pragma unroll
            for (int kc = 0; kc < 7; kc++)
                acc += tile[r + kr][c + kc] * kw[kr * 7 + kc];
        if (ch < 32) {
            y0p[i] = __float2bfloat16(__bfloat162float(pwa[i]) * acc);
        } else {
            op[i] = __float2bfloat16(acc);
        }
    }
}

// ---------------- host launch ----------------
static void launch_gemm(const bf16* W, const bf16* X, const float* bias, void* out,
                        int M, int K, const bf16* gate, int chofs,
                        const float* resid, const float* gvec, int gelu, int obf)
{
    gemm_bf16_kernel<<<dim3(8, (M + 127) / 128, BATCH), 256, GEMM_SMEM>>>(
        W, X, bias, out, M, K, gate, chofs, resid, gvec, gelu, obf);
}

extern "C" void kernel_launch(void* const* d_in, const int* in_sizes, int n_in,
                              void* d_out, int out_size)
{
    (void)in_sizes; (void)n_in; (void)out_size;
    // unconditional, identical every call (graph-capture safe, no static state)
    cudaFuncSetAttribute(gemm_bf16_kernel,
                         cudaFuncAttributeMaxDynamicSharedMemorySize, GEMM_SMEM);

    const float* x      = (const float*)d_in[0];
    const float* ln1_w  = (const float*)d_in[1];
    const float* ln1_b  = (const float*)d_in[2];
    const float* pin_w  = (const float*)d_in[3];
    const float* pin_b  = (const float*)d_in[4];
    const float* dw_w   = (const float*)d_in[5];
    const float* dw_b   = (const float*)d_in[6];
    const float* pw0_w  = (const float*)d_in[7];
    const float* pw0_b  = (const float*)d_in[8];
    const float* pw1_w  = (const float*)d_in[9];
    const float* pw1_b  = (const float*)d_in[10];
    const float* pw2_w  = (const float*)d_in[11];
    const float* pw2_b  = (const float*)d_in[12];
    const float* pw3_w  = (const float*)d_in[13];
    const float* pw3_b  = (const float*)d_in[14];
    const float* pout_w = (const float*)d_in[15];
    const float* pout_b = (const float*)d_in[16];
    const float* ln2_w  = (const float*)d_in[17];
    const float* ln2_b  = (const float*)d_in[18];
    const float* fc1_w  = (const float*)d_in[19];
    const float* fc1_b  = (const float*)d_in[20];
    const float* fc2_w  = (const float*)d_in[21];
    const float* fc2_b  = (const float*)d_in[22];
    const float* g1     = (const float*)d_in[23];
    const float* g2     = (const float*)d_in[24];
    float* out = (float*)d_out;

    bf16 *p_lnb, *p_fusedb, *p_dwb, *p_y0b, *p_y1b, *p_y2b, *p_y3b, *p_y4b, *p_ln2b, *p_hb;
    bf16 *w_pin, *w_pw0, *w_pw1, *w_pw2, *w_pw3, *w_pout, *w_fc1, *w_fc2;
    float *p_x1;
    cudaGetSymbolAddress((void**)&p_lnb,   g_lnb);
    cudaGetSymbolAddress((void**)&p_fusedb,g_fusedb);
    cudaGetSymbolAddress((void**)&p_dwb,   g_dwb);
    cudaGetSymbolAddress((void**)&p_y0b,   g_y0b);
    cudaGetSymbolAddress((void**)&p_y1b,   g_y1b);
    cudaGetSymbolAddress((void**)&p_y2b,   g_y2b);
    cudaGetSymbolAddress((void**)&p_y3b,   g_y3b);
    cudaGetSymbolAddress((void**)&p_y4b,   g_y4b);
    cudaGetSymbolAddress((void**)&p_x1,    g_x1);
    cudaGetSymbolAddress((void**)&p_ln2b,  g_ln2b);
    cudaGetSymbolAddress((void**)&p_hb,    g_hb);
    cudaGetSymbolAddress((void**)&w_pin,   g_wpin);
    cudaGetSymbolAddress((void**)&w_pw0,   g_wpw0);
    cudaGetSymbolAddress((void**)&w_pw1,   g_wpw1);
    cudaGetSymbolAddress((void**)&w_pw2,   g_wpw2);
    cudaGetSymbolAddress((void**)&w_pw3,   g_wpw3);
    cudaGetSymbolAddress((void**)&w_pout,  g_wpout);
    cudaGetSymbolAddress((void**)&w_fc1,   g_wfc1);
    cudaGetSymbolAddress((void**)&w_fc2,   g_wfc2);

    // single merged weight conversion
    conv_all<<<512, 256>>>(pin_w, w_pin, pw0_w, w_pw0, pw1_w, w_pw1, pw2_w, w_pw2,
                           pw3_w, w_pw3, pout_w, w_pout, fc1_w, w_fc1, fc2_w, w_fc2);

    dim3 lnBlock(32, 8);

    // 1) LN1 -> bf16
    ln_kernel<<<BATCH*32, lnBlock>>>(x, ln1_w, ln1_b, p_lnb);
    // 2) pin
    launch_gemm(w_pin, p_lnb, pin_b, p_fusedb, 1024, 512, nullptr, 0, nullptr, nullptr, 0, 1);
    // 3) dwconv (+ fused gate0)
    dwconv_kernel<<<dim3(DWC, BATCH), 256>>>(p_fusedb, dw_w, dw_b, p_dwb, p_y0b);
    // 4..7) gating chain
    launch_gemm(w_pw0, p_y0b, pw0_b, p_y1b,  64,  32, p_dwb,  32, nullptr, nullptr, 0, 1);
    launch_gemm(w_pw1, p_y1b, pw1_b, p_y2b, 128,  64, p_dwb,  96, nullptr, nullptr, 0, 1);
    launch_gemm(w_pw2, p_y2b, pw2_b, p_y3b, 256, 128, p_dwb, 224, nullptr, nullptr, 0, 1);
    launch_gemm(w_pw3, p_y3b, pw3_b, p_y4b, 512, 256, p_dwb, 480, nullptr, nullptr, 0, 1);
    // 8) pout + residual -> x1 (fp32)
    launch_gemm(w_pout, p_y4b, pout_b, p_x1, 512, 512, nullptr, 0, x, g1, 0, 0);
    // 9) LN2 -> bf16
    ln_kernel<<<BATCH*32, lnBlock>>>(p_x1, ln2_w, ln2_b, p_ln2b);
    // 10) fc1 + GELU -> bf16
    launch_gemm(w_fc1, p_ln2b, fc1_b, p_hb, 2048, 512, nullptr, 0, nullptr, nullptr, 1, 1);
    // 11) fc2 + residual -> out (fp32)
    launch_gemm(w_fc2, p_hb, fc2_b, out, 512, 2048, nullptr, 0, p_x1, g2, 0, 0);
}

// round 9
// speedup vs baseline: 4.8675x; 1.0757x over previous
#include <cuda_runtime.h>
#include <cuda_bf16.h>
#include <math.h>
#include <stddef.h>
#include <stdint.h>

#define BATCH 16
#define DIM   512
#define HW    1024
#define NPIX  1024
#define DWC   992

typedef __nv_bfloat16 bf16;

// -------- scratch (device globals) --------
__device__ bf16  g_lnb [(size_t)BATCH*DIM *HW];
__device__ bf16  g_fusedb[(size_t)BATCH*1024*HW];
__device__ bf16  g_dwb [(size_t)BATCH*DWC *HW];
__device__ bf16  g_y0b [(size_t)BATCH* 32 *HW];
__device__ bf16  g_y1b [(size_t)BATCH* 64 *HW];
__device__ bf16  g_y2b [(size_t)BATCH*128 *HW];
__device__ bf16  g_y3b [(size_t)BATCH*256 *HW];
__device__ bf16  g_y4b [(size_t)BATCH*512 *HW];
__device__ float g_x1  [(size_t)BATCH*DIM *HW];
__device__ bf16  g_ln2b[(size_t)BATCH*DIM *HW];
__device__ bf16  g_hb  [(size_t)BATCH*2048*HW];
// bf16 weights
__device__ bf16  g_wpin[1024*512];
__device__ bf16  g_wpw0[64*32];
__device__ bf16  g_wpw1[128*64];
__device__ bf16  g_wpw2[256*128];
__device__ bf16  g_wpw3[512*256];
__device__ bf16  g_wpout[512*512];
__device__ bf16  g_wfc1[2048*512];
__device__ bf16  g_wfc2[512*2048];

__device__ __forceinline__ uint32_t smem_u32(const void* p) {
    uint32_t a;
    asm("{ .reg .u64 t; cvta.to.shared.u64 t, %1; cvt.u32.u64 %0, t; }" : "=r"(a) : "l"(p));
    return a;
}
#define CP16Z(d, s, sz) asm volatile("cp.async.cg.shared.global [%0], [%1], 16, %2;" :: "r"(d), "l"(s), "r"(sz) : "memory")
#define CP_COMMIT() asm volatile("cp.async.commit_group;" ::: "memory")
#define CP_WAIT0()  asm volatile("cp.async.wait_group 0;" ::: "memory")
#define CP_WAIT1()  asm volatile("cp.async.wait_group 1;" ::: "memory")

// smem geometry (elements): A stage 128x72, B stage 64x136
#define A_ROWSTRIDE 72
#define B_ROWSTRIDE 136
#define A_STAGE_B   (128 * A_ROWSTRIDE * 2)                 // 18432 bytes
#define STAGE_B     (A_STAGE_B + 64 * B_ROWSTRIDE * 2)      // 35840 bytes
#define GEMM_SMEM   (2 * STAGE_B)                           // 71680 bytes

// ================= bf16 mma.sync GEMM =================
__global__ __launch_bounds__(256, 2) void gemm_bf16_kernel(
    const bf16* __restrict__ W, const bf16* __restrict__ X,
    const float* __restrict__ bias, void* __restrict__ out,
    int M, int K,
    const bf16* __restrict__ gate, int gate_chofs,
    const float* __restrict__ resid, const float* __restrict__ gvec,
    int do_gelu, int out_bf16)
{
    extern __shared__ char dsm[];
    const uint32_t sb = smem_u32(dsm);

    const int tid  = threadIdx.x;
    const int lane = tid & 31;
    const int wid  = tid >> 5;
    const int warp_m = wid >> 1;
    const int warp_n = wid & 1;

    const int bi = blockIdx.z;
    const int m0 = blockIdx.y * 128;
    const int n0 = blockIdx.x * 128;
    const bf16* Xb = X + (size_t)bi * K * NPIX;

    auto load_chunk = [&](int kc, int st) {
        uint32_t a_s = sb + st * STAGE_B;
        uint32_t b_s = a_s + A_STAGE_B;
        int k0 = kc * 64;
        #pragma unroll
        for (int i = 0; i < 4; i++) {
            int idx = tid + i * 256;
            int r = idx >> 3, c8 = idx & 7;
            int mr = m0 + r; if (mr >= M) mr = M - 1;
            int kk = k0 + c8 * 8;
            int sz = (kk < K) ? 16 : 0;
            const bf16* src = W + (size_t)mr * K + (kk < K ? kk : 0);
            CP16Z(a_s + (uint32_t)(r * A_ROWSTRIDE + c8 * 8) * 2, src, sz);
        }
        #pragma unroll
        for (int i = 0; i < 4; i++) {
            int idx = tid + i * 256;
            int kr = idx >> 4, c = idx & 15;
            int kk = k0 + kr;
            int sz = (kk < K) ? 16 : 0;
            const bf16* src = Xb + (size_t)(kk < K ? kk : 0) * NPIX + n0 + c * 8;
            CP16Z(b_s + (uint32_t)(kr * B_ROWSTRIDE + c * 8) * 2, src, sz);
        }
    };

    const int lrow = lane & 15;
    const int lc8  = (lane >> 4) << 3;

    float acc[2][8][4];
    #pragma unroll
    for (int i = 0; i < 2; i++)
        #pragma unroll
        for (int j = 0; j < 8; j++)
            #pragma unroll
            for (int k = 0; k < 4; k++) acc[i][j][k] = 0.f;

    const int KT = (K + 63) >> 6;

    load_chunk(0, 0);
    CP_COMMIT();

    for (int kt = 0; kt < KT; kt++) {
        if (kt + 1 < KT) {
            load_chunk(kt + 1, (kt + 1) & 1);
            CP_COMMIT();
            CP_WAIT1();
        } else {
            CP_WAIT0();
        }
        __syncthreads();

        uint32_t a_s = sb + (kt & 1) * STAGE_B;
        uint32_t b_s = a_s + A_STAGE_B;
        uint32_t a_base = a_s + ((warp_m * 32 + lrow) * A_ROWSTRIDE + lc8) * 2;
        uint32_t b_base = b_s + (lrow * B_ROWSTRIDE + warp_n * 64 + lc8) * 2;

        #pragma unroll
        for (int s = 0; s < 4; s++) {
            uint32_t ra[2][4], rb[4][4];
            #pragma unroll
            for (int mt = 0; mt < 2; mt++) {
                uint32_t addr = a_base + (mt * 16 * A_ROWSTRIDE + s * 16) * 2;
                asm volatile(
                    "ldmatrix.sync.aligned.m8n8.x4.shared.b16 {%0,%1,%2,%3}, [%4];"
                    : "=r"(ra[mt][0]), "=r"(ra[mt][1]), "=r"(ra[mt][2]), "=r"(ra[mt][3])
                    : "r"(addr));
            }
            #pragma unroll
            for (int nt = 0; nt < 4; nt++) {
                uint32_t addr = b_base + (s * 16 * B_ROWSTRIDE + nt * 16) * 2;
                asm volatile(
                    "ldmatrix.sync.aligned.m8n8.x4.trans.shared.b16 {%0,%1,%2,%3}, [%4];"
                    : "=r"(rb[nt][0]), "=r"(rb[nt][1]), "=r"(rb[nt][2]), "=r"(rb[nt][3])
                    : "r"(addr));
            }
            #pragma unroll
            for (int mt = 0; mt < 2; mt++) {
                #pragma unroll
                for (int nf = 0; nf < 8; nf++) {
                    uint32_t b0 = rb[nf >> 1][(nf & 1) * 2 + 0];
                    uint32_t b1 = rb[nf >> 1][(nf & 1) * 2 + 1];
                    asm volatile(
                        "mma.sync.aligned.m16n8k16.row.col.f32.bf16.bf16.f32 "
                        "{%0,%1,%2,%3}, {%4,%5,%6,%7}, {%8,%9}, {%0,%1,%2,%3};"
                        : "+f"(acc[mt][nf][0]), "+f"(acc[mt][nf][1]),
                          "+f"(acc[mt][nf][2]), "+f"(acc[mt][nf][3])
                        : "r"(ra[mt][0]), "r"(ra[mt][1]), "r"(ra[mt][2]), "r"(ra[mt][3]),
                          "r"(b0), "r"(b1));
                }
            }
        }
        __syncthreads();
    }

    // ---- epilogue ----
    const int row  = lane >> 2;
    const int colp = (lane & 3) * 2;
    #pragma unroll
    for (int mt = 0; mt < 2; mt++) {
        #pragma unroll
        for (int nf = 0; nf < 8; nf++) {
            int n = n0 + warp_n * 64 + nf * 8 + colp;
            #pragma unroll
            for (int half = 0; half < 2; half++) {
                int m = m0 + warp_m * 32 + mt * 16 + row + half * 8;
                if (m >= M) continue;
                float v0 = acc[mt][nf][half * 2 + 0];
                float v1 = acc[mt][nf][half * 2 + 1];
                float bval = bias[m];
                v0 += bval; v1 += bval;
                if (gate) {
                    const bf16* gp = gate + ((size_t)bi * DWC + gate_chofs + m) * NPIX + n;
                    v0 *= __bfloat162float(gp[0]);
                    v1 *= __bfloat162float(gp[1]);
                }
                if (do_gelu) {
                    v0 = 0.5f * v0 * (1.0f + erff(v0 * 0.70710678118654752f));
                    v1 = 0.5f * v1 * (1.0f + erff(v1 * 0.70710678118654752f));
                }
                if (resid) {
                    const float* rp = resid + ((size_t)bi * M + m) * NPIX + n;
                    float gm = gvec[m];
                    v0 = rp[0] + gm * v0;
                    v1 = rp[1] + gm * v1;
                }
                if (out_bf16) {
                    __nv_bfloat162* op = (__nv_bfloat162*)((bf16*)out + ((size_t)bi * M + m) * NPIX + n);
                    *op = __floats2bfloat162_rn(v0, v1);
                } else {
                    float2 p; p.x = v0; p.y = v1;
                    *(float2*)((float*)out + ((size_t)bi * M + m) * NPIX + n) = p;
                }
            }
        }
    }
}

// ---------------- merged weight fp32 -> bf16 (single launch, float4) ----------------
__global__ __launch_bounds__(256) void conv_all(
    const float* s0, bf16* d0, const float* s1, bf16* d1,
    const float* s2, bf16* d2, const float* s3, bf16* d3,
    const float* s4, bf16* d4, const float* s5, bf16* d5,
    const float* s6, bf16* d6, const float* s7, bf16* d7)
{
    const int n4[8] = {131072, 512, 2048, 8192, 32768, 65536, 262144, 262144};
    const float* srcs[8] = {s0, s1, s2, s3, s4, s5, s6, s7};
    bf16* dsts[8] = {d0, d1, d2, d3, d4, d5, d6, d7};
    int total = 131072 + 512 + 2048 + 8192 + 32768 + 65536 + 262144 + 262144;
    for (int i = blockIdx.x * 256 + threadIdx.x; i < total; i += gridDim.x * 256) {
        int seg = 0, off = i;
        #pragma unroll
        for (int j = 0; j < 8; j++) {
            if (off >= n4[j]) { off -= n4[j]; seg = j + 1; }
            else break;
        }
        float4 v = ((const float4*)srcs[seg])[off];
        __nv_bfloat162* dp = (__nv_bfloat162*)dsts[seg] + off * 2;
        dp[0] = __floats2bfloat162_rn(v.x, v.y);
        dp[1] = __floats2bfloat162_rn(v.z, v.w);
    }
}

// ---------------- LayerNorm (channel dim, NCHW), bf16 out ----------------
__global__ __launch_bounds__(256) void ln_kernel(
    const float* __restrict__ x, const float* __restrict__ w,
    const float* __restrict__ b, bf16* __restrict__ out)
{
    int bi  = blockIdx.x >> 5;
    int px0 = (blockIdx.x & 31) << 5;
    int tx = threadIdx.x, ty = threadIdx.y;
    const float* xb = x + (size_t)bi * DIM * HW + px0 + tx;

    float s = 0.f, ss = 0.f;
    for (int c = ty; c < DIM; c += 8) {
        float v = xb[(size_t)c * HW];
        s += v; ss += v * v;
    }
    __shared__ float Ss[8][32], Sq[8][32];
    Ss[ty][tx] = s; Sq[ty][tx] = ss;
    __syncthreads();
    if (ty == 0) {
        float a = 0.f, q = 0.f;
        #pragma unroll
        for (int i = 0; i < 8; i++) { a += Ss[i][tx]; q += Sq[i][tx]; }
        float mean = a * (1.0f / DIM);
        float var  = q * (1.0f / DIM) - mean * mean;
        Ss[0][tx] = mean;
        Sq[0][tx] = rsqrtf(var + 1e-6f);
    }
    __syncthreads();
    float mean = Ss[0][tx], inv = Sq[0][tx];
    bf16* ob = out + (size_t)bi * DIM * HW + px0 + tx;
    for (int c = ty; c < DIM; c += 8) {
        float v = xb[(size_t)c * HW];
        ob[(size_t)c * HW] = __float2bfloat16(w[c] * ((v - mean) * inv) + b[c]);
    }
}

// ---------------- 7x7 depthwise conv (+ fused gate0 for ch<32) ----------------
// 4 horizontal pixels per thread; 7x10 tile row segment cached in registers.
// Tile row stride 39 -> conflict-free banks for the 4row x 8colgroup warp pattern.
__global__ __launch_bounds__(256) void dwconv_kernel(
    const bf16* __restrict__ fused, const float* __restrict__ w,
    const float* __restrict__ bias, bf16* __restrict__ out,
    bf16* __restrict__ y0)
{
    int ch = blockIdx.x, bi = blockIdx.y;
    const bf16* ip = fused + ((size_t)bi * 1024 + 32 + ch) * HW;
    __shared__ float tile[38 * 39];
    __shared__ float kw[49];
    int tid = threadIdx.x;
    if (tid < 49) kw[tid] = w[(size_t)ch * 49 + tid];
    for (int i = tid; i < 38 * 38; i += 256) {
        int r = i / 38, c = i % 38;
        int rr = r - 3, cc = c - 3;
        tile[r * 39 + c] = (rr >= 0 && rr < 32 && cc >= 0 && cc < 32)
            ? __bfloat162float(ip[rr * 32 + cc]) : 0.f;
    }
    __syncthreads();

    const int r  = tid >> 3;         // 0..31 output row
    const int c0 = (tid & 7) * 4;    // output col group of 4
    float a0 = bias[ch], a1 = a0, a2 = a0, a3 = a0;

    #pragma unroll
    for (int kr = 0; kr < 7; kr++) {
        const float* trow = &tile[(r + kr) * 39 + c0];
        float rv[10];
        #pragma unroll
        for (int t = 0; t < 10; t++) rv[t] = trow[t];
        #pragma unroll
        for (int kc = 0; kc < 7; kc++) {
            float wv = kw[kr * 7 + kc];
            a0 += rv[kc + 0] * wv;
            a1 += rv[kc + 1] * wv;
            a2 += rv[kc + 2] * wv;
            a3 += rv[kc + 3] * wv;
        }
    }

    int i = r * 32 + c0;
    if (ch < 32) {
        const bf16* pwa = fused + ((size_t)bi * 1024 + ch) * HW + i;
        float p0 = __bfloat162float(pwa[0]);
        float p1 = __bfloat162float(pwa[1]);
        float p2 = __bfloat162float(pwa[2]);
        float p3 = __bfloat162float(pwa[3]);
        __nv_bfloat162* y0p = (__nv_bfloat162*)(y0 + ((size_t)bi * 32 + ch) * HW + i);
        y0p[0] = __floats2bfloat162_rn(p0 * a0, p1 * a1);
        y0p[1] = __floats2bfloat162_rn(p2 * a2, p3 * a3);
    } else {
        __nv_bfloat162* op = (__nv_bfloat162*)(out + ((size_t)bi * DWC + ch) * HW + i);
        op[0] = __floats2bfloat162_rn(a0, a1);
        op[1] = __floats2bfloat162_rn(a2, a3);
    }
}

// ---------------- host launch ----------------
static void launch_gemm(const bf16* W, const bf16* X, const float* bias, void* out,
                        int M, int K, const bf16* gate, int chofs,
                        const float* resid, const float* gvec, int gelu, int obf)
{
    gemm_bf16_kernel<<<dim3(8, (M + 127) / 128, BATCH), 256, GEMM_SMEM>>>(
        W, X, bias, out, M, K, gate, chofs, resid, gvec, gelu, obf);
}

extern "C" void kernel_launch(void* const* d_in, const int* in_sizes, int n_in,
                              void* d_out, int out_size)
{
    (void)in_sizes; (void)n_in; (void)out_size;
    cudaFuncSetAttribute(gemm_bf16_kernel,
                         cudaFuncAttributeMaxDynamicSharedMemorySize, GEMM_SMEM);

    const float* x      = (const float*)d_in[0];
    const float* ln1_w  = (const float*)d_in[1];
    const float* ln1_b  = (const float*)d_in[2];
    const float* pin_w  = (const float*)d_in[3];
    const float* pin_b  = (const float*)d_in[4];
    const float* dw_w   = (const float*)d_in[5];
    const float* dw_b   = (const float*)d_in[6];
    const float* pw0_w  = (const float*)d_in[7];
    const float* pw0_b  = (const float*)d_in[8];
    const float* pw1_w  = (const float*)d_in[9];
    const float* pw1_b  = (const float*)d_in[10];
    const float* pw2_w  = (const float*)d_in[11];
    const float* pw2_b  = (const float*)d_in[12];
    const float* pw3_w  = (const float*)d_in[13];
    const float* pw3_b  = (const float*)d_in[14];
    const float* pout_w = (const float*)d_in[15];
    const float* pout_b = (const float*)d_in[16];
    const float* ln2_w  = (const float*)d_in[17];
    const float* ln2_b  = (const float*)d_in[18];
    const float* fc1_w  = (const float*)d_in[19];
    const float* fc1_b  = (const float*)d_in[20];
    const float* fc2_w  = (const float*)d_in[21];
    const float* fc2_b  = (const float*)d_in[22];
    const float* g1     = (const float*)d_in[23];
    const float* g2     = (const float*)d_in[24];
    float* out = (float*)d_out;

    bf16 *p_lnb, *p_fusedb, *p_dwb, *p_y0b, *p_y1b, *p_y2b, *p_y3b, *p_y4b, *p_ln2b, *p_hb;
    bf16 *w_pin, *w_pw0, *w_pw1, *w_pw2, *w_pw3, *w_pout, *w_fc1, *w_fc2;
    float *p_x1;
    cudaGetSymbolAddress((void**)&p_lnb,   g_lnb);
    cudaGetSymbolAddress((void**)&p_fusedb,g_fusedb);
    cudaGetSymbolAddress((void**)&p_dwb,   g_dwb);
    cudaGetSymbolAddress((void**)&p_y0b,   g_y0b);
    cudaGetSymbolAddress((void**)&p_y1b,   g_y1b);
    cudaGetSymbolAddress((void**)&p_y2b,   g_y2b);
    cudaGetSymbolAddress((void**)&p_y3b,   g_y3b);
    cudaGetSymbolAddress((void**)&p_y4b,   g_y4b);
    cudaGetSymbolAddress((void**)&p_x1,    g_x1);
    cudaGetSymbolAddress((void**)&p_ln2b,  g_ln2b);
    cudaGetSymbolAddress((void**)&p_hb,    g_hb);
    cudaGetSymbolAddress((void**)&w_pin,   g_wpin);
    cudaGetSymbolAddress((void**)&w_pw0,   g_wpw0);
    cudaGetSymbolAddress((void**)&w_pw1,   g_wpw1);
    cudaGetSymbolAddress((void**)&w_pw2,   g_wpw2);
    cudaGetSymbolAddress((void**)&w_pw3,   g_wpw3);
    cudaGetSymbolAddress((void**)&w_pout,  g_wpout);
    cudaGetSymbolAddress((void**)&w_fc1,   g_wfc1);
    cudaGetSymbolAddress((void**)&w_fc2,   g_wfc2);

    conv_all<<<512, 256>>>(pin_w, w_pin, pw0_w, w_pw0, pw1_w, w_pw1, pw2_w, w_pw2,
                           pw3_w, w_pw3, pout_w, w_pout, fc1_w, w_fc1, fc2_w, w_fc2);

    dim3 lnBlock(32, 8);

    // 1) LN1 -> bf16
    ln_kernel<<<BATCH*32, lnBlock>>>(x, ln1_w, ln1_b, p_lnb);
    // 2) pin
    launch_gemm(w_pin, p_lnb, pin_b, p_fusedb, 1024, 512, nullptr, 0, nullptr, nullptr, 0, 1);
    // 3) dwconv (+ fused gate0)
    dwconv_kernel<<<dim3(DWC, BATCH), 256>>>(p_fusedb, dw_w, dw_b, p_dwb, p_y0b);
    // 4..7) gating chain
    launch_gemm(w_pw0, p_y0b, pw0_b, p_y1b,  64,  32, p_dwb,  32, nullptr, nullptr, 0, 1);
    launch_gemm(w_pw1, p_y1b, pw1_b, p_y2b, 128,  64, p_dwb,  96, nullptr, nullptr, 0, 1);
    launch_gemm(w_pw2, p_y2b, pw2_b, p_y3b, 256, 128, p_dwb, 224, nullptr, nullptr, 0, 1);
    launch_gemm(w_pw3, p_y3b, pw3_b, p_y4b, 512, 256, p_dwb, 480, nullptr, nullptr, 0, 1);
    // 8) pout + residual -> x1 (fp32)
    launch_gemm(w_pout, p_y4b, pout_b, p_x1, 512, 512, nullptr, 0, x, g1, 0, 0);
    // 9) LN2 -> bf16
    ln_kernel<<<BATCH*32, lnBlock>>>(p_x1, ln2_w, ln2_b, p_ln2b);
    // 10) fc1 + GELU -> bf16
    launch_gemm(w_fc1, p_ln2b, fc1_b, p_hb, 2048, 512, nullptr, 0, nullptr, nullptr, 1, 1);
    // 11) fc2 + residual -> out (fp32)
    launch_gemm(w_fc2, p_hb, fc2_b, out, 512, 2048, nullptr, 0, p_x1, g2, 0, 0);
}